// round 11
// baseline (speedup 1.0000x reference)
#include <cuda_runtime.h>
#include <cuda_bf16.h>

// IntensitiyTransform: out[b,h,w,c] = it[b, clamp(round(255*im[b,h,w,c]),0,255), c]
// im: [16,512,512,3] f32   it: [16,256,3] f32   out: [16,512,512,3] f32
//
// R9 ncu: occ 79.8%, issue 28.0% (flat vs R4 despite +occupancy), L1 51.2% top.
// -> binder is per-iteration LDS latency exposure, not occupancy.
// R10/R11 experiment (unmeasured, resubmitted): flat-phase ILP. Per thread:
//   phase 1: 6x LDG.128 front-batched        (MLP=6)
//   phase 2: all 24 LUT addresses            (cvt.rni.sat.u8 fused round+clamp)
//   phase 3: all 24 LDS issued back-to-back  (one pipelined latency window)
//   phase 4: assemble + 6x STG.128 streaming (__stcs, evict-first)
// Reg budget ~56-72; 64 warps/SM allows 128 regs -> 8 CTAs/SM without a clamp.

#define THREADS 256
#define BLOCKS_PER_BATCH 128
#define ITERS 6   // 196608 float4s / (128*256) threads == 6 exactly

// round-to-nearest-even + saturate to [0,255] in one F2I
static __device__ __forceinline__ int idx_u8(float f) {
    unsigned short r;
    asm("cvt.rni.sat.u8.f32 %0, %1;" : "=h"(r) : "f"(f));
    return (int)r;
}

static __global__ __launch_bounds__(THREADS)
void intensity_lut_kernel(const float* __restrict__ im,
                          const float* __restrict__ it,
                          float* __restrict__ out) {
    __shared__ __align__(16) float lut[768];  // [256][3]

    const int b = blockIdx.y;

    // Stage LUT: 768 floats = 192 float4s; threads 0..191 move one each.
    const float4* __restrict__ it4 = reinterpret_cast<const float4*>(it) + b * 192;
    if (threadIdx.x < 192)
        reinterpret_cast<float4*>(lut)[threadIdx.x] = it4[threadIdx.x];
    __syncthreads();

    const int PER_BATCH4 = (512 * 512 * 3) / 4;        // 196608
    const int stride     = BLOCKS_PER_BATCH * THREADS; // 32768

    const float4* __restrict__ im4  = reinterpret_cast<const float4*>(im)  + (size_t)b * PER_BATCH4;
    float4* __restrict__       out4 = reinterpret_cast<float4*>(out)       + (size_t)b * PER_BATCH4;

    const int base = blockIdx.x * THREADS + threadIdx.x;

    // ---- phase 1: front-batch all 6 wide loads (MLP=6)
    float4 v[ITERS];
    #pragma unroll
    for (int k = 0; k < ITERS; k++)
        v[k] = im4[base + k * stride];

    // ---- phase 2: compute all 24 LUT element-offsets
    // Channel of element 4*i is i%3; i advances by stride, stride%3==2, so the
    // channel phase rotates by -1 (mod 3) per iteration.
    int a[ITERS * 4];
    {
        int c0 = base % 3;
        #pragma unroll
        for (int k = 0; k < ITERS; k++) {
            int c1 = c0 + 1; if (c1 == 3) c1 = 0;
            int c2 = c1 + 1; if (c2 == 3) c2 = 0;
            a[4*k + 0] = idx_u8(255.0f * v[k].x) * 3 + c0;
            a[4*k + 1] = idx_u8(255.0f * v[k].y) * 3 + c1;
            a[4*k + 2] = idx_u8(255.0f * v[k].z) * 3 + c2;
            a[4*k + 3] = idx_u8(255.0f * v[k].w) * 3 + c0;  // elem 4i+3: channel c0
            c0 = c0 - 1; if (c0 < 0) c0 = 2;                // phase -1 mod 3
        }
    }

    // ---- phase 3: issue all 24 independent shared-memory gathers
    float r[ITERS * 4];
    #pragma unroll
    for (int j = 0; j < ITERS * 4; j++)
        r[j] = lut[a[j]];

    // ---- phase 4: assemble and stream out
    #pragma unroll
    for (int k = 0; k < ITERS; k++) {
        float4 o;
        o.x = r[4*k + 0];
        o.y = r[4*k + 1];
        o.z = r[4*k + 2];
        o.w = r[4*k + 3];
        __stcs(&out4[base + k * stride], o);   // evict-first: keep input in L2
    }
}

extern "C" void kernel_launch(void* const* d_in, const int* in_sizes, int n_in,
                              void* d_out, int out_size) {
    const float* im = (const float*)d_in[0];   // [16,512,512,3]
    const float* it = (const float*)d_in[1];   // [16,256,3]
    float* out = (float*)d_out;

    dim3 grid(BLOCKS_PER_BATCH, 16);
    intensity_lut_kernel<<<grid, THREADS>>>(im, it, out);
}